// round 7
// baseline (speedup 1.0000x reference)
#include <cuda_runtime.h>
#include <math.h>
#include <stdint.h>

#define BS 16
#define TT 20
#define NN 512
#define EE 64
#define LL 8
#define STEPS 12
#define NROWS 19   // rows of skill_seq used as S-row indices (0..18)

// ---------------- scratch (device globals; no allocation allowed) ----------
__device__ float g_S[BS * 2 * NROWS * NN];   // S[b][k][r][n] = adj[k,b,sh_r,n] + adj2[k,b,sh_r,n]
__device__ float g_hA[BS * NN * EE];
__device__ float g_hB[BS * NN * EE];
__device__ float g_ew[STEPS * BS * LL];      // exp(-dtw)

// ---------------- helpers --------------------------------------------------
__device__ __forceinline__ float tanh_fast(float x) {
    float e = __expf(2.0f * x);
    return 1.0f - __fdividef(2.0f, e + 1.0f);
}

__device__ __forceinline__ float warp_sum(float v) {
#pragma unroll
    for (int o = 16; o > 0; o >>= 1) v += __shfl_xor_sync(0xffffffffu, v, o);
    return v;
}

// packed f32x2 FMA: d = a*b + d
__device__ __forceinline__ void fma2(unsigned long long& d,
                                     unsigned long long a,
                                     unsigned long long b) {
    asm("fma.rn.f32x2 %0, %1, %2, %0;" : "+l"(d) : "l"(a), "l"(b));
}
__device__ __forceinline__ float red2(unsigned long long p) {
    float2 r;
    asm("mov.b64 {%0,%1}, %2;" : "=f"(r.x), "=f"(r.y) : "l"(p));
    return r.x + r.y;
}

__device__ __forceinline__ uint32_t f2tf32(float v) {
    uint32_t u;
    asm("cvt.rna.tf32.f32 %0, %1;" : "=r"(u) : "f"(v));
    return u;
}

__device__ __forceinline__ void mma_tf32(float& c0, float& c1, float& c2, float& c3,
                                         uint32_t a0, uint32_t a1, uint32_t a2, uint32_t a3,
                                         uint32_t b0, uint32_t b1) {
    asm("mma.sync.aligned.m16n8k8.row.col.f32.tf32.tf32.f32 "
        "{%0,%1,%2,%3},{%4,%5,%6,%7},{%8,%9},{%0,%1,%2,%3};"
        : "+f"(c0), "+f"(c1), "+f"(c2), "+f"(c3)
        : "r"(a0), "r"(a1), "r"(a2), "r"(a3), "r"(b0), "r"(b1));
}

// ---------------- hidden0 --------------------------------------------------
__global__ void k_init_hidden(const int* __restrict__ skill,
                              const int* __restrict__ label,
                              const float* __restrict__ emb,
                              float* __restrict__ hid) {
    int b = blockIdx.x;
    int n = blockIdx.y * 4 + (threadIdx.x >> 6);
    int e = threadIdx.x & 63;
    float v = 0.0f;
#pragma unroll
    for (int l = LL - 1; l >= 0; --l) {
        if (skill[b * TT + l] == n) {
            float lp = (label[b * TT + l] == 0) ? -1.0f : 1.0f;
            v = emb[n * EE + e] * lp;
            break;
        }
    }
    hid[(b * NN + n) * EE + e] = v;
}

// ---------------- exp(-dtw) ------------------------------------------------
__global__ void k_ew(const int* __restrict__ timeq) {
    int idx = blockIdx.x * blockDim.x + threadIdx.x;
    if (idx >= STEPS * BS * LL) return;
    int l = idx % LL;
    int b = (idx / LL) % BS;
    int t = idx / (LL * BS);
    float d = fabsf((float)timeq[b * TT + t + l] - (float)timeq[b * TT + t + LL]) + 1e-6f;
    float dtw = logf(d) / logf(5.0f);
    g_ew[idx] = expf(-dtw);
}

// ---------------- S rows: adj + adj@adj/N, only the 19 needed rows ---------
__global__ void k_S(const int* __restrict__ skill, const float* __restrict__ adj) {
    int chunk = blockIdx.x, k = blockIdx.y, b = blockIdx.z;
    int n = chunk * 128 + threadIdx.x;

    __shared__ float arows[NROWS][NN];
    __shared__ int rowskill[NROWS];
    if (threadIdx.x < NROWS) rowskill[threadIdx.x] = skill[b * TT + threadIdx.x];
    __syncthreads();

    const float* A = adj + ((size_t)k * BS + b) * NN * NN;
    for (int idx = threadIdx.x; idx < NROWS * NN; idx += 128) {
        int r = idx >> 9;
        int j = idx & 511;
        arows[r][j] = A[rowskill[r] * NN + j];
    }
    __syncthreads();

    float acc[NROWS];
#pragma unroll
    for (int r = 0; r < NROWS; r++) acc[r] = 0.0f;

#pragma unroll 4
    for (int j = 0; j < NN; j++) {
        float c = A[j * NN + n];
#pragma unroll
        for (int r = 0; r < NROWS; r++) acc[r] += arows[r][j] * c;
    }

    const float inv = 1.0f / (float)NN;
#pragma unroll
    for (int r = 0; r < NROWS; r++) {
        g_S[(((size_t)b * 2 + k) * NROWS + r) * NN + n] = arows[r][n] + acc[r] * inv;
    }
}

// ---------------- f-network at target node (one warp) ----------------------
__device__ __forceinline__ void fnet_warp(
    float x0, float x1, int lane, float* sx,
    const float* __restrict__ fw1, const float* __restrict__ fb1,
    const float* __restrict__ ln1g, const float* __restrict__ ln1b,
    const float* __restrict__ fw2, const float* __restrict__ fb2,
    const float* __restrict__ ln2g, const float* __restrict__ ln2b,
    const float* __restrict__ fw3, const float* __restrict__ fb3,
    float* __restrict__ outp) {

    __syncwarp();
    sx[lane] = x0; sx[lane + 32] = x1;
    __syncwarp();
    float t0 = fb1[lane], t1 = fb1[lane + 32];
#pragma unroll 8
    for (int f = 0; f < 64; f++) {
        float v = sx[f];
        t0 += v * fw1[lane * 64 + f];
        t1 += v * fw1[(lane + 32) * 64 + f];
    }
    float h0 = x0 + (t0 > 0.0f ? t0 : 0.01f * t0);
    float h1 = x1 + (t1 > 0.0f ? t1 : 0.01f * t1);

    float m = warp_sum(h0 + h1) * (1.0f / 64.0f);
    float d0 = h0 - m, d1 = h1 - m;
    float var = warp_sum(d0 * d0 + d1 * d1) * (1.0f / 64.0f);
    float r = rsqrtf(var + 1e-5f);
    float y0 = d0 * r * ln1g[lane] + ln1b[lane];
    float y1 = d1 * r * ln1g[lane + 32] + ln1b[lane + 32];

    __syncwarp();
    sx[lane] = y0; sx[lane + 32] = y1;
    __syncwarp();
    t0 = fb2[lane]; t1 = fb2[lane + 32];
#pragma unroll 8
    for (int f = 0; f < 64; f++) {
        float v = sx[f];
        t0 += v * fw2[lane * 64 + f];
        t1 += v * fw2[(lane + 32) * 64 + f];
    }
    h0 += (t0 > 0.0f ? t0 : 0.01f * t0);
    h1 += (t1 > 0.0f ? t1 : 0.01f * t1);

    m = warp_sum(h0 + h1) * (1.0f / 64.0f);
    d0 = h0 - m; d1 = h1 - m;
    var = warp_sum(d0 * d0 + d1 * d1) * (1.0f / 64.0f);
    r = rsqrtf(var + 1e-5f);
    float z0 = d0 * r * ln2g[lane] + ln2b[lane];
    float z1 = d1 * r * ln2g[lane + 32] + ln2b[lane + 32];

    float l0 = warp_sum(z0 * fw3[lane] + z1 * fw3[lane + 32]);
    float l1 = warp_sum(z0 * fw3[64 + lane] + z1 * fw3[64 + lane + 32]);
    if (lane == 0) {
        l0 += fb3[0]; l1 += fb3[1];
        *outp = 1.0f / (1.0f + expf(l0 - l1));
    }
    __syncwarp();
}

// ---------------- fused step kernel (tensor-core fc2) -----------------------
// grid (32, BS), block 256 = 8 warps. Each warp owns 2 nodes = one m16 tile
// of the fc2 GEMM (16 rows (n,l) x 64 e x 64 f) done with 64 tf32 mma.
// smem (floats):
//   sW1b 4352 | sW2 4352 (tf32-rounded) | sM1 8*1088 | sA 512 | sHH 512 |
//   sHB 512 | sB2 64 | sEW 8 | sSH 8       total 19024 fl = 76096 B -> 3/SM
#define SW_STRIDE 68
#define M1W (16 * SW_STRIDE)       // 1088 floats per warp
#define SMEM_FLOATS 19024
#define SMEM_BYTES  (SMEM_FLOATS * 4)

__global__ __launch_bounds__(256) void k_step(
    const float* __restrict__ hcur, float* __restrict__ hnext, int t,
    const int* __restrict__ skill,
    const float* __restrict__ fc1w, const float* __restrict__ fc1b,
    const float* __restrict__ fc2w, const float* __restrict__ fc2b,
    const float* __restrict__ fw1, const float* __restrict__ fb1,
    const float* __restrict__ ln1g, const float* __restrict__ ln1b,
    const float* __restrict__ fw2, const float* __restrict__ fb2,
    const float* __restrict__ ln2g, const float* __restrict__ ln2b,
    const float* __restrict__ fw3, const float* __restrict__ fb3,
    float* __restrict__ out) {

    extern __shared__ float s[];
    float* sW1b = s;                  // [e][f] stride 68 (fp32)
    float* sW2  = s + 4352;           // [e][f] stride 68 (tf32-rounded fp32)
    float* sM1  = s + 8704;           // per-warp [16 rows][64] stride 68
    float* sA   = s + 17408;          // [8 l][64 e]
    float* sHH  = s + 17920;          // per-warp hh row (phase 1)
    float* sHB  = s + 18432;          // per-warp hidden row / fnet scratch
    float* sB2  = s + 18944;
    float* sEW  = s + 19008;
    int*   sSH  = (int*)(s + 19016);

    int b = blockIdx.y;
    int g = blockIdx.x;
    int tid = threadIdx.x;
    int w = tid >> 5;
    int lane = tid & 31;
    int gid = lane >> 2;      // mma group id (row within tile)
    int tig = lane & 3;       // thread-in-group (col/k)

    // --- stage W1b (fp32) and W2 (tf32-rounded) into smem ---
    for (int idx = tid; idx < 64 * 64; idx += 256) {
        int e = idx >> 6, f = idx & 63;
        sW1b[e * SW_STRIDE + f] = fc1w[e * 128 + 64 + f];
        sW2[e * SW_STRIDE + f]  = __uint_as_float(f2tf32(fc2w[idx]));
    }
    if (tid < 64) sB2[tid] = fc2b[tid];
    if (tid < 8) {
        sEW[tid] = g_ew[(t * BS + b) * LL + tid];
        sSH[tid] = skill[b * TT + t + tid];
    }
    __syncthreads();

    // --- phase 1: warp w computes A[w][:] = hh[w] @ W1a^T + b1 (W1a via L2) ---
    {
        int sl = sSH[w];
        sHH[w * 64 + lane]      = hcur[((b << 9) + sl) * EE + lane];
        sHH[w * 64 + lane + 32] = hcur[((b << 9) + sl) * EE + lane + 32];
        __syncwarp();
        const ulonglong2* wa0 = (const ulonglong2*)(fc1w + lane * 128);
        const ulonglong2* wa1 = (const ulonglong2*)(fc1w + (lane + 32) * 128);
        const unsigned long long* hv = (const unsigned long long*)(sHH + w * 64);
        unsigned long long a0 = 0ull, a1 = 0ull;
#pragma unroll
        for (int fp = 0; fp < 16; fp++) {
            ulonglong2 qa = __ldg(&wa0[fp]);
            ulonglong2 qb = __ldg(&wa1[fp]);
            unsigned long long m01 = hv[2 * fp], m23 = hv[2 * fp + 1];
            fma2(a0, m01, qa.x); fma2(a0, m23, qa.y);
            fma2(a1, m01, qb.x); fma2(a1, m23, qb.y);
        }
        sA[w * 64 + lane]      = red2(a0) + __ldg(&fc1b[lane]);
        sA[w * 64 + lane + 32] = red2(a1) + __ldg(&fc1b[lane + 32]);
    }
    __syncthreads();

    int tgt = __ldg(&skill[b * TT + t + LL]);
    float* myM1 = sM1 + w * M1W;
    float* mysx = sHB + w * 64;
    const unsigned long long* hv = (const unsigned long long*)mysx;
    const unsigned long long* w1bA = (const unsigned long long*)(sW1b + lane * SW_STRIDE);
    const unsigned long long* w1bB = (const unsigned long long*)(sW1b + (lane + 32) * SW_STRIDE);

    int pair = (g << 3) + w;          // [0,256)
    int n0 = pair << 1;               // warp's two nodes: n0, n0+1

    // --- G1 + msg1 (tf32) for both nodes -> myM1 rows [i*8+l][f] ---
#pragma unroll
    for (int i = 0; i < 2; i++) {
        int n = n0 + i;
        mysx[lane]      = hcur[((b << 9) + n) * EE + lane];
        mysx[lane + 32] = hcur[((b << 9) + n) * EE + lane + 32];
        __syncwarp();
        unsigned long long bp0 = 0ull, bp1 = 0ull;
#pragma unroll
        for (int fp = 0; fp < 16; fp++) {
            unsigned long long m01 = hv[2 * fp], m23 = hv[2 * fp + 1];
            fma2(bp0, m01, w1bA[2 * fp]); fma2(bp0, m23, w1bA[2 * fp + 1]);
            fma2(bp1, m01, w1bB[2 * fp]); fma2(bp1, m23, w1bB[2 * fp + 1]);
        }
        float B0 = red2(bp0), B1 = red2(bp1);
#pragma unroll
        for (int l = 0; l < 8; l++) {
            int row = i * 8 + l;
            myM1[row * SW_STRIDE + lane] =
                __uint_as_float(f2tf32(tanh_fast(sA[l * 64 + lane] + B0)));
            myM1[row * SW_STRIDE + lane + 32] =
                __uint_as_float(f2tf32(tanh_fast(sA[l * 64 + lane + 32] + B1)));
        }
        __syncwarp();
    }

    // --- fc2 as tf32 mma: 16 rows x 64 cols x 64 k ---
    float acc[8][4];
#pragma unroll
    for (int nt = 0; nt < 8; nt++) {
        acc[nt][0] = 0.f; acc[nt][1] = 0.f; acc[nt][2] = 0.f; acc[nt][3] = 0.f;
    }
    const uint32_t* m1u = (const uint32_t*)myM1;
    const uint32_t* w2u = (const uint32_t*)sW2;
#pragma unroll
    for (int kk = 0; kk < 8; kk++) {
        int col = kk * 8 + tig;
        uint32_t a0 = m1u[gid * SW_STRIDE + col];
        uint32_t a1 = m1u[(gid + 8) * SW_STRIDE + col];
        uint32_t a2 = m1u[gid * SW_STRIDE + col + 4];
        uint32_t a3 = m1u[(gid + 8) * SW_STRIDE + col + 4];
#pragma unroll
        for (int nt = 0; nt < 8; nt++) {
            uint32_t b0v = w2u[(nt * 8 + gid) * SW_STRIDE + col];
            uint32_t b1v = w2u[(nt * 8 + gid) * SW_STRIDE + col + 4];
            mma_tf32(acc[nt][0], acc[nt][1], acc[nt][2], acc[nt][3],
                     a0, a1, a2, a3, b0v, b1v);
        }
    }

    // --- epilogue on fragments: bias -> tanh -> *ew ; stage msg2 in myM1 ---
    {
        float ewl = sEW[gid];   // row l = gid for both nodes
#pragma unroll
        for (int nt = 0; nt < 8; nt++) {
            int e0 = nt * 8 + 2 * tig;
            float be0 = sB2[e0], be1 = sB2[e0 + 1];
            float2 v0, v1;
            v0.x = tanh_fast(acc[nt][0] + be0) * ewl;   // node0
            v0.y = tanh_fast(acc[nt][1] + be1) * ewl;
            v1.x = tanh_fast(acc[nt][2] + be0) * ewl;   // node1
            v1.y = tanh_fast(acc[nt][3] + be1) * ewl;
            *(float2*)(myM1 + gid * SW_STRIDE + e0) = v0;
            *(float2*)(myM1 + (gid + 8) * SW_STRIDE + e0) = v1;
        }
    }
    __syncwarp();

    // --- aggregate over l with S weights; write new_hidden; pred at tgt ---
#pragma unroll
    for (int i = 0; i < 2; i++) {
        int n = n0 + i;
        float wr0[8], wr1[8];
#pragma unroll
        for (int l = 0; l < 8; l++) {
            wr0[l] = __ldg(&g_S[(((size_t)b * 2 + 0) * NROWS + (t + l)) * NN + n]);
            wr1[l] = __ldg(&g_S[(((size_t)b * 2 + 1) * NROWS + (t + l)) * NN + n]);
        }
        float ag00 = 0, ag01 = 0, ag10 = 0, ag11 = 0;
#pragma unroll
        for (int l = 0; l < 8; l++) {
            float m0 = myM1[(i * 8 + l) * SW_STRIDE + lane];
            float m1v = myM1[(i * 8 + l) * SW_STRIDE + lane + 32];
            ag00 += wr0[l] * m0;  ag01 += wr0[l] * m1v;
            ag10 += wr1[l] * m0;  ag11 += wr1[l] * m1v;
        }
        hnext[((b << 9) + n) * EE + lane]      = 0.5f * (ag00 + ag10);
        hnext[((b << 9) + n) * EE + lane + 32] = 0.5f * (ag01 + ag11);

        if (n == tgt) {
            fnet_warp(ag00, ag01, lane, mysx, fw1, fb1, ln1g, ln1b,
                      fw2, fb2, ln2g, ln2b, fw3, fb3,
                      &out[(t * BS + b) * 2 + 0]);
            fnet_warp(ag10, ag11, lane, mysx, fw1, fb1, ln1g, ln1b,
                      fw2, fb2, ln2g, ln2b, fw3, fb3,
                      &out[(t * BS + b) * 2 + 1]);
        }
        __syncwarp();
    }
}

// ---------------- launch ----------------------------------------------------
extern "C" void kernel_launch(void* const* d_in, const int* in_sizes, int n_in,
                              void* d_out, int out_size) {
    const int*   skill = (const int*)d_in[0];
    const int*   timeq = (const int*)d_in[1];
    const int*   label = (const int*)d_in[2];
    const float* adj   = (const float*)d_in[3];
    const float* emb   = (const float*)d_in[4];
    const float* fc1w  = (const float*)d_in[5];
    const float* fc1b  = (const float*)d_in[6];
    const float* fc2w  = (const float*)d_in[7];
    const float* fc2b  = (const float*)d_in[8];
    const float* fw1   = (const float*)d_in[9];
    const float* fb1   = (const float*)d_in[10];
    const float* ln1g  = (const float*)d_in[11];
    const float* ln1b  = (const float*)d_in[12];
    const float* fw2   = (const float*)d_in[13];
    const float* fb2   = (const float*)d_in[14];
    const float* ln2g  = (const float*)d_in[15];
    const float* ln2b  = (const float*)d_in[16];
    const float* fw3   = (const float*)d_in[17];
    const float* fb3   = (const float*)d_in[18];
    float* out = (float*)d_out;

    cudaFuncSetAttribute(k_step, cudaFuncAttributeMaxDynamicSharedMemorySize, SMEM_BYTES);

    float *hA, *hB;
    cudaGetSymbolAddress((void**)&hA, g_hA);
    cudaGetSymbolAddress((void**)&hB, g_hB);

    k_init_hidden<<<dim3(BS, NN / 4), 256>>>(skill, label, emb, hA);
    k_ew<<<3, 512>>>(timeq);
    k_S<<<dim3(4, 2, BS), 128>>>(skill, adj);

    for (int t = 0; t < STEPS; t++) {
        const float* hc = (t & 1) ? hB : hA;
        float*       hn = (t & 1) ? hA : hB;
        k_step<<<dim3(32, BS), 256, SMEM_BYTES>>>(
            hc, hn, t, skill,
            fc1w, fc1b, fc2w, fc2b,
            fw1, fb1, ln1g, ln1b, fw2, fb2, ln2g, ln2b, fw3, fb3,
            out);
    }
}